// round 2
// baseline (speedup 1.0000x reference)
#include <cuda_runtime.h>

// LIF neuron: per-neuron serial scan over T=100 contiguous timesteps.
// x: [B=32, N=16384, T=100] float32, out: same shape, spikes in {0.0, 1.0}.
// decay = 1 - 1/TAU = 0.5, V_TH = 0.5.
//
// One thread per neuron row (524288 rows). Each row is 100 floats = 25 float4,
// 16B-aligned (row stride 400 B). Vectorized loads/stores; branch-free update.

#define T_STEPS 100
#define N_VEC   (T_STEPS / 4)   // 25 float4 per row

__global__ __launch_bounds__(256) void lif_kernel(const float* __restrict__ x,
                                                  float* __restrict__ out,
                                                  int n_rows) {
    int row = blockIdx.x * blockDim.x + threadIdx.x;
    if (row >= n_rows) return;

    const float4* __restrict__ xr  = reinterpret_cast<const float4*>(x)   + (long long)row * N_VEC;
    float4* __restrict__       outr = reinterpret_cast<float4*>(out)       + (long long)row * N_VEC;

    const float decay = 0.5f;
    const float vth   = 0.5f;

    float v = 0.0f;

    #pragma unroll
    for (int i = 0; i < N_VEC; ++i) {
        float4 xi = __ldg(&xr[i]);
        float4 so;

        v = fmaf(v, decay, xi.x);
        so.x = (v > vth) ? 1.0f : 0.0f;
        v = fmaf(so.x, -vth, v);

        v = fmaf(v, decay, xi.y);
        so.y = (v > vth) ? 1.0f : 0.0f;
        v = fmaf(so.y, -vth, v);

        v = fmaf(v, decay, xi.z);
        so.z = (v > vth) ? 1.0f : 0.0f;
        v = fmaf(so.z, -vth, v);

        v = fmaf(v, decay, xi.w);
        so.w = (v > vth) ? 1.0f : 0.0f;
        v = fmaf(so.w, -vth, v);

        outr[i] = so;
    }
}

extern "C" void kernel_launch(void* const* d_in, const int* in_sizes, int n_in,
                              void* d_out, int out_size) {
    const float* x = (const float*)d_in[0];
    float* out = (float*)d_out;

    // total elements = B*N*T; rows = total / T
    int n_rows = in_sizes[0] / T_STEPS;   // 32*16384 = 524288

    int threads = 256;
    int blocks = (n_rows + threads - 1) / threads;
    lif_kernel<<<blocks, threads>>>(x, out, n_rows);
}